// round 9
// baseline (speedup 1.0000x reference)
#include <cuda_runtime.h>
#include <cuda_fp16.h>
#include <cstdint>

// ================= configuration =================
#define MAXTOK 32768
#define DOUT   1024
#define MT     128           // tokens per tile
#define NT     128           // output cols per tile
#define KT     64            // k (halves) per stage
#define RSH    72            // smem row stride in halves (64 + 8 pad) = 144B
#define NSTG   3

// smem byte offsets
#define ASTG   (MT * RSH * 2)            // 18432 per stage
#define BSTG   (NT * RSH * 2)            // 18432 per stage
#define OFF_B  (NSTG * ASTG)             // 55296
#define OFF_POS  (OFF_B + NSTG * BSTG)   // 110592
#define OFF_BIAS (OFF_POS + MT * 4)      // 111104
#define SMEM_DYN (OFF_BIAS + NT * 4)     // 111616

#define SSTEP  (16 * RSH * 2)            // 16-row step in stage buffer (bytes)

// fp16 staging offsets (halves)
#define AH0 0ull
#define AH1 (AH0 + 32768ull*1536)
#define AH2 (AH1 + 32768ull*1024)
#define AH3 (AH2 + 32768ull*512)
#define AHT (AH3 + 32768ull*256)
#define WH0 0ull
#define WH1 (WH0 + 1024ull*1536)
#define WH2 (WH1 + 1024ull*1024)
#define WH3 (WH2 + 1024ull*512)
#define WHT (WH3 + 1024ull*256)

// ================= device scratch =================
__device__ int    g_cnt[4];
__device__ int    g_idx[4 * MAXTOK];
__device__ __half g_Ah[AHT];   // bucket-ordered gathered embeddings (fp16)
__device__ __half g_Wth[WHT];  // W transposed to [n][k], fp16

// ================= helpers =================
__device__ __forceinline__ uint32_t s2u(const void* p) {
    uint32_t a;
    asm("{ .reg .u64 t; cvta.to.shared.u64 t, %1; cvt.u32.u64 %0, t; }"
        : "=r"(a) : "l"(p));
    return a;
}
__device__ __forceinline__ void cp16(uint32_t dst, const void* src) {
    asm volatile("cp.async.cg.shared.global [%0], [%1], 16;"
                 :: "r"(dst), "l"(src) : "memory");
}
__device__ __forceinline__ void ldsm4(unsigned& r0, unsigned& r1,
                                      unsigned& r2, unsigned& r3, uint32_t a) {
    asm volatile("ldmatrix.sync.aligned.m8n8.x4.shared.b16 {%0,%1,%2,%3}, [%4];"
                 : "=r"(r0), "=r"(r1), "=r"(r2), "=r"(r3) : "r"(a));
}

// ================= bucketing (block-aggregated atomics) =================
__global__ void bucket_kernel(const int* __restrict__ tok,
                              const int* __restrict__ cat, int n) {
    __shared__ int h[4], h2[4], base[4];
    const int tid = threadIdx.x;
    const int t = blockIdx.x * blockDim.x + tid;
    if (tid < 4) { h[tid] = 0; h2[tid] = 0; }
    __syncthreads();
    int c = -1;
    if (t < n) {
        c = __ldg(&cat[tok[t]]);
        atomicAdd(&h[c], 1);
    }
    __syncthreads();
    if (tid < 4 && h[tid] > 0) base[tid] = atomicAdd(&g_cnt[tid], h[tid]);
    __syncthreads();
    if (t < n) {
        int r = atomicAdd(&h2[c], 1);
        g_idx[c * MAXTOK + base[c] + r] = t;
    }
}

// ================= W transpose + fp16 =================
__global__ void wt_kernel(const float* __restrict__ W0, const float* __restrict__ W1,
                          const float* __restrict__ W2, const float* __restrict__ W3) {
    const int c = blockIdx.z;
    const float* W; int dk; size_t off;
    switch (c) {
        case 0:  W = W0; dk = 1536; off = WH0; break;
        case 1:  W = W1; dk = 1024; off = WH1; break;
        case 2:  W = W2; dk = 512;  off = WH2; break;
        default: W = W3; dk = 256;  off = WH3; break;
    }
    int k0 = blockIdx.y * 32;
    if (k0 >= dk) return;
    int n0 = blockIdx.x * 32;
    __shared__ float t[32][33];
#pragma unroll
    for (int j = 0; j < 32; j += 8) {
        int k = k0 + threadIdx.y + j;
        t[threadIdx.y + j][threadIdx.x] =
            (k < dk) ? W[(size_t)k * DOUT + n0 + threadIdx.x] : 0.f;
    }
    __syncthreads();
#pragma unroll
    for (int j = 0; j < 32; j += 8) {
        int n = n0 + threadIdx.y + j;
        int k = k0 + threadIdx.x;
        if (k < dk)
            g_Wth[off + (size_t)n * dk + k] = __float2half_rn(t[threadIdx.x][threadIdx.y + j]);
    }
}

// ================= pre-gather: E rows -> bucket-ordered fp16 =================
__global__ void __launch_bounds__(256)
pregather_kernel(const int* __restrict__ tok,
                 const float* __restrict__ E0, const float* __restrict__ E1,
                 const float* __restrict__ E2, const float* __restrict__ E3) {
    const int c = blockIdx.y;
    const int s = blockIdx.x * 8 + (threadIdx.x >> 5);
    if (s >= g_cnt[c]) return;
    const int lane = threadIdx.x & 31;

    const float* E; int dk; size_t off;
    switch (c) {
        case 0:  E = E0; dk = 1536; off = AH0; break;
        case 1:  E = E1; dk = 1024; off = AH1; break;
        case 2:  E = E2; dk = 512;  off = AH2; break;
        default: E = E3; dk = 256;  off = AH3; break;
    }
    const int vid = __ldg(&tok[g_idx[c * MAXTOK + s]]);
    const float* src = E + (size_t)vid * dk;
    __half* dst = g_Ah + off + (size_t)s * dk;

    for (int i = lane * 4; i < dk; i += 128) {
        float4 v = *(const float4*)(src + i);
        __half2 h0 = __floats2half2_rn(v.x, v.y);
        __half2 h1 = __floats2half2_rn(v.z, v.w);
        *(uint2*)(dst + i) = make_uint2(*(uint32_t*)&h0, *(uint32_t*)&h1);
    }
}

// == grouped GEMM: 128 thr, 4 warps 2x2, warp tile 64x64, KT=64, 3-stage ======
__global__ void __launch_bounds__(128, 2)
gemm_kernel(const float* __restrict__ B0, const float* __restrict__ B1,
            const float* __restrict__ B2, const float* __restrict__ B3,
            float* __restrict__ out) {
    const int c   = blockIdx.z;
    const int cnt = g_cnt[c];
    const int m0  = blockIdx.y * MT;
    if (m0 >= cnt) return;
    const int n0  = blockIdx.x * NT;

    const float* BV; int dk; size_t aoff0, woff;
    switch (c) {
        case 0:  BV = B0; dk = 1536; aoff0 = AH0; woff = WH0; break;
        case 1:  BV = B1; dk = 1024; aoff0 = AH1; woff = WH1; break;
        case 2:  BV = B2; dk = 512;  aoff0 = AH2; woff = WH2; break;
        default: BV = B3; dk = 256;  aoff0 = AH3; woff = WH3; break;
    }
    const __half* Ah = g_Ah + aoff0;
    const __half* Wh = g_Wth + woff;

    extern __shared__ char sm[];
    const uint32_t sA = s2u(sm);
    int*   s_pos  = (int*)(sm + OFF_POS);
    float* s_bias = (float*)(sm + OFF_BIAS);

    const int tid = threadIdx.x;
    {   // 128 threads load 128 pos + 128 bias
        int m = m0 + tid;
        s_pos[tid] = g_idx[c * MAXTOK + (m < cnt ? m : m0)];
        s_bias[tid] = BV[n0 + tid];
    }
    __syncthreads();

    // ---- cp.async slots: 8 A + 8 B chunks per thread per stage ----
    // thread -> base row r0 = tid>>3 (0..15), kc = tid&7; rows r0+16j
    const int r0 = tid >> 3, kc = tid & 7;
    const __half* apB = Ah + (size_t)(m0 + r0) * dk + kc * 8;
    const __half* bpB = Wh + (size_t)(n0 + r0) * dk + kc * 8;
    const uint32_t dA0 = sA + (r0 * RSH + kc * 8) * 2;
    const uint32_t dB0 = sA + OFF_B + (r0 * RSH + kc * 8) * 2;
    const size_t gStep = (size_t)16 * dk;   // 16 rows in gmem (halves)

    const int lane = tid & 31, warp = tid >> 5;
    const int g = lane >> 2, t4 = lane & 3;
    const int wm = (warp >> 1) * 64;   // 2 warp-rows x 64
    const int wn = (warp & 1) * 64;    // 2 warp-cols x 64

    // ldmatrix lane addressing (byte offsets within stage buffer)
    const uint32_t aLd = sA +
        ((wm + (lane & 15)) * RSH + (lane >> 4) * 8) * 2;
    const uint32_t bLd = sA + OFF_B +
        ((wn + ((lane >> 4) & 1) * 8 + (lane & 7)) * RSH + ((lane >> 3) & 1) * 8) * 2;

    float acc[4][8][4];
#pragma unroll
    for (int mi = 0; mi < 4; mi++)
#pragma unroll
        for (int nf = 0; nf < 8; nf++)
#pragma unroll
            for (int r = 0; r < 4; r++) acc[mi][nf][r] = 0.f;

    const int nK = dk / KT;

#define ISSUE(kt) do {                                                  \
        const int _b = (kt) % NSTG;                                     \
        const int _k = (kt) * KT;                                       \
        _Pragma("unroll")                                               \
        for (int j = 0; j < 8; j++) {                                   \
            cp16(dA0 + _b * ASTG + j * SSTEP, apB + (size_t)j * gStep + _k); \
            cp16(dB0 + _b * BSTG + j * SSTEP, bpB + (size_t)j * gStep + _k); \
        }                                                               \
        asm volatile("cp.async.commit_group;" ::: "memory");            \
    } while (0)

    ISSUE(0);
    ISSUE(1);

    for (int kt = 0; kt < nK; kt++) {
        if (kt < nK - 1)
            asm volatile("cp.async.wait_group 1;" ::: "memory");
        else
            asm volatile("cp.async.wait_group 0;" ::: "memory");
        __syncthreads();

        if (kt + 2 < nK) ISSUE(kt + 2);   // DMA overlaps this stage's compute

        const uint32_t aS = aLd + (kt % NSTG) * ASTG;
        const uint32_t bS = bLd + (kt % NSTG) * BSTG;

#pragma unroll
        for (int ks = 0; ks < 4; ks++) {          // four k16 steps per stage
            const uint32_t ko = ks * 32;          // 16 halves = 32 bytes
            unsigned a[4][4], b[4][4];
#pragma unroll
            for (int mi = 0; mi < 4; mi++)
                ldsm4(a[mi][0], a[mi][1], a[mi][2], a[mi][3],
                      aS + mi * SSTEP + ko);
#pragma unroll
            for (int p = 0; p < 4; p++)
                ldsm4(b[p][0], b[p][1], b[p][2], b[p][3],
                      bS + p * SSTEP + ko);
#pragma unroll
            for (int mi = 0; mi < 4; mi++)
#pragma unroll
                for (int nf = 0; nf < 8; nf++) {
                    const unsigned b0 = b[nf >> 1][(nf & 1) * 2];
                    const unsigned b1 = b[nf >> 1][(nf & 1) * 2 + 1];
                    asm volatile(
                        "mma.sync.aligned.m16n8k16.row.col.f32.f16.f16.f32 "
                        "{%0,%1,%2,%3},{%4,%5,%6,%7},{%8,%9},{%0,%1,%2,%3};"
                        : "+f"(acc[mi][nf][0]), "+f"(acc[mi][nf][1]),
                          "+f"(acc[mi][nf][2]), "+f"(acc[mi][nf][3])
                        : "r"(a[mi][0]), "r"(a[mi][1]), "r"(a[mi][2]), "r"(a[mi][3]),
                          "r"(b0), "r"(b1));
                }
        }
    }
#undef ISSUE

    // epilogue: add bias, scatter by token position
#pragma unroll
    for (int mi = 0; mi < 4; mi++) {
        int r = wm + mi * 16 + g;
        bool ok0 = (m0 + r)     < cnt;
        bool ok1 = (m0 + r + 8) < cnt;
        long p0 = ok0 ? s_pos[r]     : 0;
        long p1 = ok1 ? s_pos[r + 8] : 0;
#pragma unroll
        for (int nf = 0; nf < 8; nf++) {
            int col = wn + nf * 8 + t4 * 2;
            float b0 = s_bias[col], b1 = s_bias[col + 1];
            if (ok0) {
                float2 v = make_float2(acc[mi][nf][0] + b0, acc[mi][nf][1] + b1);
                *(float2*)(out + p0 * DOUT + n0 + col) = v;
            }
            if (ok1) {
                float2 v = make_float2(acc[mi][nf][2] + b0, acc[mi][nf][3] + b1);
                *(float2*)(out + p1 * DOUT + n0 + col) = v;
            }
        }
    }
}

// ================= launch =================
extern "C" void kernel_launch(void* const* d_in, const int* in_sizes, int n_in,
                              void* d_out, int out_size) {
    const int*   tok = (const int*)d_in[0];
    const int*   cat = (const int*)d_in[1];
    const float* E0 = (const float*)d_in[2];
    const float* W0 = (const float*)d_in[3];
    const float* B0 = (const float*)d_in[4];
    const float* E1 = (const float*)d_in[5];
    const float* W1 = (const float*)d_in[6];
    const float* B1 = (const float*)d_in[7];
    const float* E2 = (const float*)d_in[8];
    const float* W2 = (const float*)d_in[9];
    const float* B2 = (const float*)d_in[10];
    const float* E3 = (const float*)d_in[11];
    const float* W3 = (const float*)d_in[12];
    const float* B3 = (const float*)d_in[13];
    float* out = (float*)d_out;

    int n = in_sizes[0];  // 32768

    cudaFuncSetAttribute(gemm_kernel,
                         cudaFuncAttributeMaxDynamicSharedMemorySize, SMEM_DYN);

    void* cntp = nullptr;
    cudaGetSymbolAddress(&cntp, g_cnt);
    cudaMemsetAsync(cntp, 0, 4 * sizeof(int));

    bucket_kernel<<<(n + 255) / 256, 256>>>(tok, cat, n);                // k1
    wt_kernel<<<dim3(32, 48, 4), dim3(32, 8)>>>(W0, W1, W2, W3);         // k2
    pregather_kernel<<<dim3(MAXTOK / 8, 4), 256>>>(tok, E0, E1, E2, E3); // k3

    dim3 grid(DOUT / NT, MAXTOK / MT, 4);
    gemm_kernel<<<grid, 128, SMEM_DYN>>>(B0, B1, B2, B3, out);           // k4 (profiled)
}

// round 10
// speedup vs baseline: 1.0114x; 1.0114x over previous
#include <cuda_runtime.h>
#include <cuda_fp16.h>
#include <cstdint>

// ================= configuration =================
#define MAXTOK 32768
#define DOUT   1024
#define MT     128
#define NT     128
#define KT     64            // k (halves) per stage
#define RSH    72            // smem row stride in halves (64 + 8 pad) = 144B
#define NSTG   3

// smem byte offsets
#define ASTG   (MT * RSH * 2)            // 18432 per stage
#define BSTG   (NT * RSH * 2)            // 18432 per stage
#define OFF_B  (NSTG * ASTG)             // 55296
#define OFF_POS  (OFF_B + NSTG * BSTG)   // 110592
#define OFF_BIAS (OFF_POS + MT * 4)      // 111104
#define SMEM_DYN (OFF_BIAS + NT * 4 + 16)// 112128 (incl tile slot)

// fp16 staging offsets (halves)
#define AH0 0ull
#define AH1 (AH0 + 32768ull*1536)
#define AH2 (AH1 + 32768ull*1024)
#define AH3 (AH2 + 32768ull*512)
#define AHT (AH3 + 32768ull*256)
#define WH0 0ull
#define WH1 (WH0 + 1024ull*1536)
#define WH2 (WH1 + 1024ull*1024)
#define WH3 (WH2 + 1024ull*512)
#define WHT (WH3 + 1024ull*256)

#define WT_BLKS 6144         // 32*48*4 transpose blocks
#define PG_BLKS 16384        // 4096*4 pregather blocks

// ================= device scratch =================
// g_ctl: [0..3]=cnt, [4]=bucket ticket, [5]=queue next, [6]=ntiles, [7]=pad
__device__ int    g_ctl[8];
__device__ int    g_idx[4 * MAXTOK];
__device__ unsigned g_tiles[4 * (MAXTOK / MT) * (DOUT / NT)];
__device__ __half g_Ah[AHT];
__device__ __half g_Wth[WHT];

// ================= helpers =================
__device__ __forceinline__ uint32_t s2u(const void* p) {
    uint32_t a;
    asm("{ .reg .u64 t; cvta.to.shared.u64 t, %1; cvt.u32.u64 %0, t; }"
        : "=r"(a) : "l"(p));
    return a;
}
__device__ __forceinline__ void cp16(uint32_t dst, const void* src) {
    asm volatile("cp.async.cg.shared.global [%0], [%1], 16;"
                 :: "r"(dst), "l"(src) : "memory");
}
__device__ __forceinline__ void ldsm4(unsigned& r0, unsigned& r1,
                                      unsigned& r2, unsigned& r3, uint32_t a) {
    asm volatile("ldmatrix.sync.aligned.m8n8.x4.shared.b16 {%0,%1,%2,%3}, [%4];"
                 : "=r"(r0), "=r"(r1), "=r"(r2), "=r"(r3) : "r"(a));
}

// ============ bucketing (block-aggregated) + tile-list build ============
__global__ void bucket_kernel(const int* __restrict__ tok,
                              const int* __restrict__ cat, int n) {
    __shared__ int h[4], h2[4], base[4];
    __shared__ int lastblk;
    const int tid = threadIdx.x;
    const int t = blockIdx.x * blockDim.x + tid;
    if (tid < 4) { h[tid] = 0; h2[tid] = 0; }
    __syncthreads();
    int c = -1;
    if (t < n) {
        c = __ldg(&cat[tok[t]]);
        atomicAdd(&h[c], 1);
    }
    __syncthreads();
    if (tid < 4 && h[tid] > 0) base[tid] = atomicAdd(&g_ctl[tid], h[tid]);
    __syncthreads();
    if (t < n) {
        int r = atomicAdd(&h2[c], 1);
        g_idx[c * MAXTOK + base[c] + r] = t;
    }
    // ticket: last block builds the tile list (all cnts final by then)
    __threadfence();
    __syncthreads();
    if (tid == 0) {
        int tk = atomicAdd(&g_ctl[4], 1);
        lastblk = (tk == (int)gridDim.x - 1);
    }
    __syncthreads();
    if (lastblk) {
        int b[5];
        b[0] = 0;
#pragma unroll
        for (int cc = 0; cc < 4; cc++) {
            int mt = (g_ctl[cc] + MT - 1) / MT;
            b[cc + 1] = b[cc] + mt * (DOUT / NT);
        }
        for (int i = tid; i < b[4]; i += blockDim.x) {
            int cc = 0;
            while (i >= b[cc + 1]) cc++;
            int rel = i - b[cc];
            g_tiles[i] = ((unsigned)cc << 20) | ((unsigned)(rel >> 3) << 8)
                       | (unsigned)(rel & 7);
        }
        if (tid == 0) g_ctl[6] = b[4];
    }
}

// ======== prep: fused W-transpose(+fp16) and embedding pre-gather ========
__global__ void __launch_bounds__(256)
prep_kernel(const int* __restrict__ tok,
            const float* __restrict__ E0, const float* __restrict__ E1,
            const float* __restrict__ E2, const float* __restrict__ E3,
            const float* __restrict__ W0, const float* __restrict__ W1,
            const float* __restrict__ W2, const float* __restrict__ W3) {
    const int bx = blockIdx.x;
    const int tid = threadIdx.x;
    if (bx < WT_BLKS) {
        // ---- W transpose + fp16 ----
        const int c = bx / 1536;
        const int r = bx % 1536;
        const int nx = r & 31, ky = r >> 5;
        const float* W; int dk; size_t off;
        switch (c) {
            case 0:  W = W0; dk = 1536; off = WH0; break;
            case 1:  W = W1; dk = 1024; off = WH1; break;
            case 2:  W = W2; dk = 512;  off = WH2; break;
            default: W = W3; dk = 256;  off = WH3; break;
        }
        int k0 = ky * 32;
        if (k0 >= dk) return;
        int n0 = nx * 32;
        __shared__ float tbuf[32][33];
        const int tx = tid & 31, ty = tid >> 5;
#pragma unroll
        for (int j = 0; j < 32; j += 8) {
            int k = k0 + ty + j;
            tbuf[ty + j][tx] = (k < dk) ? W[(size_t)k * DOUT + n0 + tx] : 0.f;
        }
        __syncthreads();
#pragma unroll
        for (int j = 0; j < 32; j += 8) {
            int nn = n0 + ty + j;
            int k = k0 + tx;
            if (k < dk)
                g_Wth[off + (size_t)nn * dk + k] = __float2half_rn(tbuf[tx][ty + j]);
        }
    } else {
        // ---- pre-gather: E rows -> bucket-ordered fp16 ----
        const int q = bx - WT_BLKS;
        const int c = q >> 12;            // 4096 blocks per category
        const int xb = q & 4095;
        const int s = xb * 8 + (tid >> 5);
        if (s >= g_ctl[c]) return;
        const int lane = tid & 31;
        const float* E; int dk; size_t off;
        switch (c) {
            case 0:  E = E0; dk = 1536; off = AH0; break;
            case 1:  E = E1; dk = 1024; off = AH1; break;
            case 2:  E = E2; dk = 512;  off = AH2; break;
            default: E = E3; dk = 256;  off = AH3; break;
        }
        const int vid = __ldg(&tok[g_idx[c * MAXTOK + s]]);
        const float* src = E + (size_t)vid * dk;
        __half* dst = g_Ah + off + (size_t)s * dk;
        for (int i = lane * 4; i < dk; i += 128) {
            float4 v = *(const float4*)(src + i);
            __half2 h0 = __floats2half2_rn(v.x, v.y);
            __half2 h1 = __floats2half2_rn(v.z, v.w);
            *(uint2*)(dst + i) = make_uint2(*(uint32_t*)&h0, *(uint32_t*)&h1);
        }
    }
}

// ===== persistent grouped GEMM (fp16 m16n8k16 + ldmatrix, work queue) ========
__global__ void __launch_bounds__(256, 2)
gemm_kernel(const float* __restrict__ B0, const float* __restrict__ B1,
            const float* __restrict__ B2, const float* __restrict__ B3,
            float* __restrict__ out) {
    extern __shared__ char sm[];
    const uint32_t sA = s2u(sm);
    int*   s_pos  = (int*)(sm + OFF_POS);
    float* s_bias = (float*)(sm + OFF_BIAS);
    int*   s_tile = (int*)(sm + OFF_BIAS + NT * 4);

    const int tid  = threadIdx.x;
    const int lane = tid & 31, warp = tid >> 5;
    const int g = lane >> 2, t4 = lane & 3;
    const int wm = (warp >> 2) * 64;   // 2 warp-rows x 64
    const int wn = (warp & 3) * 32;    // 4 warp-cols x 32

    const int r0 = tid >> 3, kc = tid & 7;
    const uint32_t dA0 = sA + (r0 * RSH + kc * 8) * 2;
    const uint32_t dB0 = sA + OFF_B + (r0 * RSH + kc * 8) * 2;
    const uint32_t aLd = sA + ((wm + (lane & 15)) * RSH + (lane >> 4) * 8) * 2;
    const uint32_t bLd = sA + OFF_B +
        ((wn + ((lane >> 4) & 1) * 8 + (lane & 7)) * RSH + ((lane >> 3) & 1) * 8) * 2;

    const int ntiles = g_ctl[6];

    for (;;) {
        if (tid == 0) *s_tile = atomicAdd(&g_ctl[5], 1);
        __syncthreads();                // also fences prior tile's s_pos reads
        const int t = *s_tile;
        if (t >= ntiles) break;

        const unsigned e = g_tiles[t];
        const int c  = e >> 20;
        const int m0 = (int)((e >> 8) & 0xFFF) * MT;
        const int n0 = (int)(e & 0xFF) * NT;
        const int cnt = g_ctl[c];

        const float* BV; int dk; size_t aoff, woff;
        switch (c) {
            case 0:  BV = B0; dk = 1536; aoff = AH0; woff = WH0; break;
            case 1:  BV = B1; dk = 1024; aoff = AH1; woff = WH1; break;
            case 2:  BV = B2; dk = 512;  aoff = AH2; woff = WH2; break;
            default: BV = B3; dk = 256;  aoff = AH3; woff = WH3; break;
        }
        const __half* Ah = g_Ah + aoff;
        const __half* Wh = g_Wth + woff;

        if (tid < MT) {
            int m = m0 + tid;
            s_pos[tid] = g_idx[c * MAXTOK + (m < cnt ? m : m0)];
            s_bias[tid] = BV[n0 + tid];
        }
        __syncthreads();

        // cp.async gmem pointers for this tile (4 A + 4 B rows per thread)
        const __half* ap[4];
        const __half* bp[4];
#pragma unroll
        for (int j = 0; j < 4; j++) {
            int row = r0 + 32 * j;
            ap[j] = Ah + (size_t)(m0 + row) * dk + kc * 8;
            bp[j] = Wh + (size_t)(n0 + row) * dk + kc * 8;
        }

        float acc[4][4][4];
#pragma unroll
        for (int mi = 0; mi < 4; mi++)
#pragma unroll
            for (int nf = 0; nf < 4; nf++)
#pragma unroll
                for (int r = 0; r < 4; r++) acc[mi][nf][r] = 0.f;

        const int nK = dk / KT;

#define ISSUE(kt) do {                                                  \
        const int _b = (kt) % NSTG;                                     \
        const int _k = (kt) * KT;                                       \
        cp16(dA0 + _b * ASTG,                 ap[0] + _k);              \
        cp16(dA0 + _b * ASTG + 32*RSH*2,      ap[1] + _k);              \
        cp16(dA0 + _b * ASTG + 64*RSH*2,      ap[2] + _k);              \
        cp16(dA0 + _b * ASTG + 96*RSH*2,      ap[3] + _k);              \
        cp16(dB0 + _b * BSTG,                 bp[0] + _k);              \
        cp16(dB0 + _b * BSTG + 32*RSH*2,      bp[1] + _k);              \
        cp16(dB0 + _b * BSTG + 64*RSH*2,      bp[2] + _k);              \
        cp16(dB0 + _b * BSTG + 96*RSH*2,      bp[3] + _k);              \
        asm volatile("cp.async.commit_group;" ::: "memory");            \
    } while (0)

        ISSUE(0);
        ISSUE(1);

        for (int kt = 0; kt < nK; kt++) {
            if (kt < nK - 1)
                asm volatile("cp.async.wait_group 1;" ::: "memory");
            else
                asm volatile("cp.async.wait_group 0;" ::: "memory");
            __syncthreads();

            if (kt + 2 < nK) ISSUE(kt + 2);

            const uint32_t aS = aLd + (kt % NSTG) * ASTG;
            const uint32_t bS = bLd + (kt % NSTG) * BSTG;

#pragma unroll
            for (int ks = 0; ks < 4; ks++) {
                const uint32_t ko = ks * 32;
                unsigned a[4][4], b[2][4];
#pragma unroll
                for (int mi = 0; mi < 4; mi++)
                    ldsm4(a[mi][0], a[mi][1], a[mi][2], a[mi][3],
                          aS + mi * (16 * RSH * 2) + ko);
#pragma unroll
                for (int p = 0; p < 2; p++)
                    ldsm4(b[p][0], b[p][1], b[p][2], b[p][3],
                          bS + p * (16 * RSH * 2) + ko);
#pragma unroll
                for (int mi = 0; mi < 4; mi++)
#pragma unroll
                    for (int nf = 0; nf < 4; nf++) {
                        const unsigned b0 = b[nf >> 1][(nf & 1) * 2];
                        const unsigned b1 = b[nf >> 1][(nf & 1) * 2 + 1];
                        asm volatile(
                            "mma.sync.aligned.m16n8k16.row.col.f32.f16.f16.f32 "
                            "{%0,%1,%2,%3},{%4,%5,%6,%7},{%8,%9},{%0,%1,%2,%3};"
                            : "+f"(acc[mi][nf][0]), "+f"(acc[mi][nf][1]),
                              "+f"(acc[mi][nf][2]), "+f"(acc[mi][nf][3])
                            : "r"(a[mi][0]), "r"(a[mi][1]), "r"(a[mi][2]),
                              "r"(a[mi][3]), "r"(b0), "r"(b1));
                    }
            }
        }
#undef ISSUE

        // epilogue: add bias, scatter by token position
#pragma unroll
        for (int mi = 0; mi < 4; mi++) {
            int r = wm + mi * 16 + g;
            bool ok0 = (m0 + r)     < cnt;
            bool ok1 = (m0 + r + 8) < cnt;
            long p0 = ok0 ? s_pos[r]     : 0;
            long p1 = ok1 ? s_pos[r + 8] : 0;
#pragma unroll
            for (int nf = 0; nf < 4; nf++) {
                int col = wn + nf * 8 + t4 * 2;
                float b0 = s_bias[col], b1 = s_bias[col + 1];
                if (ok0) {
                    float2 v = make_float2(acc[mi][nf][0] + b0, acc[mi][nf][1] + b1);
                    *(float2*)(out + p0 * DOUT + n0 + col) = v;
                }
                if (ok1) {
                    float2 v = make_float2(acc[mi][nf][2] + b0, acc[mi][nf][3] + b1);
                    *(float2*)(out + p1 * DOUT + n0 + col) = v;
                }
            }
        }
    }
}

// ================= launch =================
extern "C" void kernel_launch(void* const* d_in, const int* in_sizes, int n_in,
                              void* d_out, int out_size) {
    const int*   tok = (const int*)d_in[0];
    const int*   cat = (const int*)d_in[1];
    const float* E0 = (const float*)d_in[2];
    const float* W0 = (const float*)d_in[3];
    const float* B0 = (const float*)d_in[4];
    const float* E1 = (const float*)d_in[5];
    const float* W1 = (const float*)d_in[6];
    const float* B1 = (const float*)d_in[7];
    const float* E2 = (const float*)d_in[8];
    const float* W2 = (const float*)d_in[9];
    const float* B2 = (const float*)d_in[10];
    const float* E3 = (const float*)d_in[11];
    const float* W3 = (const float*)d_in[12];
    const float* B3 = (const float*)d_in[13];
    float* out = (float*)d_out;

    int n = in_sizes[0];  // 32768

    cudaFuncSetAttribute(gemm_kernel,
                         cudaFuncAttributeMaxDynamicSharedMemorySize, SMEM_DYN);

    void* ctlp = nullptr;
    cudaGetSymbolAddress(&ctlp, g_ctl);
    cudaMemsetAsync(ctlp, 0, 8 * sizeof(int));                          // 1

    bucket_kernel<<<(n + 255) / 256, 256>>>(tok, cat, n);                // 2
    prep_kernel<<<WT_BLKS + PG_BLKS, 256>>>(tok, E0, E1, E2, E3,
                                            W0, W1, W2, W3);             // 3

    gemm_kernel<<<304, 256, SMEM_DYN>>>(B0, B1, B2, B3, out);            // 4 (profiled)
}